// round 6
// baseline (speedup 1.0000x reference)
#include <cuda_runtime.h>

// LIF spike neuron scan — cp.async (LDGSTS) smem-staged streaming version.
// x: [B,S,N] fp32, m0: [B,N] fp32.
// out (fp32): spikes [B,S,N] flattened, then m_final [B,N].
// B=32, S=1024, N=2048.

#define B_DIM 32
#define S_DIM 1024
#define N_DIM 2048
#define DECAY 0.8f
#define THRESH 0.5f

#define BLK 64                   // threads per block = chains per block
#define TS 32                    // timesteps staged per pipeline stage
#define NSTAGES (S_DIM / TS)     // 32
#define NBUF 3                   // triple buffer: 2 stages in flight during compute
#define CHUNKS_PER_THREAD ((TS * BLK) / (BLK * 4))  // 8 x 16B per thread per stage

__device__ __forceinline__ void cp_async16(void* smem_dst, const void* gmem_src) {
    unsigned saddr = (unsigned)__cvta_generic_to_shared(smem_dst);
    asm volatile("cp.async.cg.shared.global [%0], [%1], 16;\n"
                 :: "r"(saddr), "l"(gmem_src) : "memory");
}
__device__ __forceinline__ void cp_commit() {
    asm volatile("cp.async.commit_group;\n" ::: "memory");
}

__global__ __launch_bounds__(BLK) void lif_scan_kernel(
    const float* __restrict__ x,
    const float* __restrict__ m0,
    float* __restrict__ out)
{
    __shared__ float buf[NBUF][TS][BLK];   // 3 * 8KB = 24KB

    const int tid = threadIdx.x;
    const int idx = blockIdx.x * BLK + tid;          // b*N + n
    const int b  = idx >> 11;                        // / N_DIM
    const int n0 = (blockIdx.x * BLK) & (N_DIM - 1); // block's first n (block-uniform b)

    const float* __restrict__ xblk = x + (size_t)b * S_DIM * N_DIM + n0; // row t at +t*N
    float* __restrict__ sp   = out + (size_t)b * S_DIM * N_DIM + (n0 + tid);
    float* __restrict__ mfin = out + (size_t)B_DIM * S_DIM * N_DIM;

    // ---- stage issue: copy TS rows x 256B into buf[s % NBUF] ----
    auto issue_stage = [&](int s) {
        float* dst = &buf[s % NBUF][0][0];
        const float* src = xblk + (size_t)s * TS * N_DIM;
        #pragma unroll
        for (int j = 0; j < CHUNKS_PER_THREAD; j++) {
            int m = j * BLK + tid;        // 16B-chunk index within the 8KB tile
            int r = m >> 4;               // row (timestep within stage)
            int c = m & 15;               // 16B chunk within row
            cp_async16(dst + (size_t)m * 4,
                       src + (size_t)r * N_DIM + (size_t)c * 4);
        }
        cp_commit();
    };

    // Prologue: fill the pipeline (stages 0,1,2 in flight)
    issue_stage(0);
    issue_stage(1);
    issue_stage(2);

    float m = m0[idx];

    #pragma unroll 1
    for (int s = 0; s < NSTAGES; s++) {
        // Wait until stage s is complete (pending groups = stages > s only)
        if (s + 2 < NSTAGES)      asm volatile("cp.async.wait_group 2;\n" ::: "memory");
        else if (s + 1 < NSTAGES) asm volatile("cp.async.wait_group 1;\n" ::: "memory");
        else                      asm volatile("cp.async.wait_group 0;\n" ::: "memory");
        __syncthreads();

        const float (*cb)[BLK] = buf[s % NBUF];
        float* spst = sp + (size_t)s * TS * N_DIM;

        #pragma unroll
        for (int k = 0; k < TS; k++) {
            m = DECAY * m + cb[k][tid];
            const bool fire = (m > THRESH);
            __stcs(spst + (size_t)k * N_DIM, fire ? 1.0f : 0.0f);
            m = fire ? 0.0f : m;
        }

        __syncthreads();   // all threads done reading buf[s%NBUF]

        if (s + NBUF < NSTAGES)
            issue_stage(s + NBUF);   // refill the buffer just consumed
    }

    mfin[idx] = m;
}

extern "C" void kernel_launch(void* const* d_in, const int* in_sizes, int n_in,
                              void* d_out, int out_size)
{
    const float* x  = (const float*)d_in[0];
    const float* m0 = (const float*)d_in[1];
    float* out = (float*)d_out;

    const int total = B_DIM * N_DIM;   // 65536 chains
    const int blocks = total / BLK;    // 1024 blocks of 64 threads
    lif_scan_kernel<<<blocks, BLK>>>(x, m0, out);
}

// round 7
// speedup vs baseline: 1.0863x; 1.0863x over previous
#include <cuda_runtime.h>

// LIF spike neuron scan — float2-vectorized register-double-buffered version.
// Each thread owns 2 adjacent chains. x: [B,S,N] fp32, m0: [B,N] fp32.
// out (fp32): spikes [B,S,N] flattened, then m_final [B,N].
// B=32, S=1024, N=2048.

#define B_DIM 32
#define S_DIM 1024
#define N_DIM 2048
#define DECAY 0.8f
#define THRESH 0.5f
#define U 16            // timesteps per pipeline stage
#define BLK 32          // threads per block (1 warp) -> near-perfect CTA balance

#define N2 (N_DIM / 2)  // float2 columns per row

__global__ __launch_bounds__(BLK) void lif_scan_kernel(
    const float* __restrict__ x,
    const float* __restrict__ m0,
    float* __restrict__ out)
{
    const int p = blockIdx.x * BLK + threadIdx.x;   // float2-chain index, 0..32767
    const int b  = p >> 10;                         // / N2
    const int n2 = p & (N2 - 1);                    // % N2

    const float2* __restrict__ xp =
        (const float2*)(x + (size_t)b * S_DIM * N_DIM) + n2;
    float2* __restrict__ sp =
        (float2*)(out + (size_t)b * S_DIM * N_DIM) + n2;
    const float2* __restrict__ m0p = (const float2*)m0 + p;
    float2* __restrict__ mfin =
        (float2*)(out + (size_t)B_DIM * S_DIM * N_DIM) + p;

    float2 mv = *m0p;
    float mx = mv.x, my = mv.y;

    float2 a[U], bb[U];

    // Prologue: load stage 0
    #pragma unroll
    for (int k = 0; k < U; k++)
        a[k] = __ldcs(xp + (size_t)k * N2);

    #pragma unroll 1
    for (int t = 0; t < S_DIM; t += 2 * U) {
        // Prefetch stage t+U while computing stage t
        #pragma unroll
        for (int k = 0; k < U; k++)
            bb[k] = __ldcs(xp + (size_t)(t + U + k) * N2);

        #pragma unroll
        for (int k = 0; k < U; k++) {
            mx = DECAY * mx + a[k].x;
            my = DECAY * my + a[k].y;
            const bool fx = (mx > THRESH);
            const bool fy = (my > THRESH);
            __stcs(sp + (size_t)(t + k) * N2,
                   make_float2(fx ? 1.0f : 0.0f, fy ? 1.0f : 0.0f));
            mx = fx ? 0.0f : mx;
            my = fy ? 0.0f : my;
        }

        // Prefetch stage t+2U (guarded) while computing stage t+U
        if (t + 2 * U < S_DIM) {
            #pragma unroll
            for (int k = 0; k < U; k++)
                a[k] = __ldcs(xp + (size_t)(t + 2 * U + k) * N2);
        }

        #pragma unroll
        for (int k = 0; k < U; k++) {
            mx = DECAY * mx + bb[k].x;
            my = DECAY * my + bb[k].y;
            const bool fx = (mx > THRESH);
            const bool fy = (my > THRESH);
            __stcs(sp + (size_t)(t + U + k) * N2,
                   make_float2(fx ? 1.0f : 0.0f, fy ? 1.0f : 0.0f));
            mx = fx ? 0.0f : mx;
            my = fy ? 0.0f : my;
        }
    }

    *mfin = make_float2(mx, my);
}

extern "C" void kernel_launch(void* const* d_in, const int* in_sizes, int n_in,
                              void* d_out, int out_size)
{
    const float* x  = (const float*)d_in[0];
    const float* m0 = (const float*)d_in[1];
    float* out = (float*)d_out;

    const int total2 = (B_DIM * N_DIM) / 2;   // 32768 float2 chains
    const int blocks = total2 / BLK;          // 1024 blocks of 32 threads
    lif_scan_kernel<<<blocks, BLK>>>(x, m0, out);
}